// round 4
// baseline (speedup 1.0000x reference)
#include <cuda_runtime.h>
#include <cuda_bf16.h>
#include <math.h>

// ---------------- constants ----------------
#define TOPK        1000
#define CAND_CAP    2048
#define HB          65536
#define ORD_SHIFT   16
#define MCAP        (1 << 17)
#define NMS_T       0.6f
#define CONF_T      0.05f
#define CTR_CLAMP_F 32.0f
#define STRIDE_F    32.0f
#define SCALE_CLAMP_F 4.1351666f   // log(1000/16) fp32

#define NBLK  132
#define NTHR  512

// ---------------- device scratch ----------------
__device__ unsigned int       g_ordered[MCAP];
__device__ int                g_label[MCAP];
__device__ unsigned int       g_hist[HB];
__device__ unsigned long long g_cand[CAND_CAP];
__device__ int                g_ncand;
__device__ int                g_B;
__device__ float4             g_tbox[1024];
__device__ float4             g_obox[1024];
__device__ float              g_area[1024];
__device__ float              g_tscore[1024];
__device__ int                g_tlabel[1024];
__device__ unsigned char      g_tvalid[1024];
__device__ unsigned long long g_maskT[16 * 1024];   // maskT[w*1024 + i]

// grid barrier state
__device__ unsigned int g_bar_count = 0;
__device__ unsigned int g_bar_gen   = 0;

__device__ __forceinline__ void grid_bar() {
    __syncthreads();
    if (threadIdx.x == 0) {
        __threadfence();
        volatile unsigned int* vgen = &g_bar_gen;
        unsigned int gen = *vgen;
        unsigned int t = atomicAdd(&g_bar_count, 1u);
        if (t == (unsigned)(gridDim.x - 1)) {
            g_bar_count = 0;
            __threadfence();
            *vgen = gen + 1u;
        } else {
            while (*vgen == gen) __nanosleep(64);
        }
        __threadfence();
    }
    __syncthreads();
}

__device__ __forceinline__ unsigned int f2ord(float f) {
    unsigned int u = __float_as_uint(f);
    return (u & 0x80000000u) ? ~u : (u | 0x80000000u);
}
__device__ __forceinline__ float ord2f(unsigned int o) {
    unsigned int u = (o & 0x80000000u) ? (o & 0x7FFFFFFFu) : ~o;
    return __uint_as_float(u);
}

__device__ __forceinline__ void score_row(const float* __restrict__ row, int C, int lane,
                                          float& v, int& bi) {
    v = -INFINITY; bi = 0;
    for (int c = lane; c < C; c += 32) {
        float x = row[c];
        if (x > v) { v = x; bi = c; }
    }
    #pragma unroll
    for (int off = 16; off > 0; off >>= 1) {
        float ov = __shfl_down_sync(0xffffffffu, v, off);
        int   ob = __shfl_down_sync(0xffffffffu, bi, off);
        if (ov > v || (ov == v && ob < bi)) { v = ov; bi = ob; }
    }
}

// =====================================================================
__global__ __launch_bounds__(NTHR, 1) void fused_yolof(
    const float* __restrict__ cls, const float* __restrict__ reg,
    const float* __restrict__ anchor_size,
    const int* __restrict__ pH, const int* __restrict__ pW,
    int h_fb, int w_fb, int A, int M, int C,
    float* __restrict__ out)
{
    __shared__ unsigned long long s_u64[CAND_CAP];          // 16KB, phase-aliased
    __shared__ unsigned long long s_validw[16], s_rem[16], s_keep[16];

    const int bid  = blockIdx.x;
    const int tid  = threadIdx.x;
    const int gtid = bid * NTHR + tid;
    const int nthr = NBLK * NTHR;
    const int lane = tid & 31;
    const int wid  = tid >> 5;
    const int gw   = gtid >> 5;
    const int NW   = nthr >> 5;

    // ---------- phase 0: zero ----------
    for (int i = gtid; i < HB; i += nthr) g_hist[i] = 0;
    for (int i = gtid; i < CAND_CAP; i += nthr) g_cand[i] = 0ULL;
    if (gtid < 1024) {
        g_tbox[gtid]   = make_float4(0.f, 0.f, 0.f, 0.f);
        g_obox[gtid]   = make_float4(0.f, 0.f, 0.f, 0.f);
        g_area[gtid]   = 0.f;
        g_tscore[gtid] = 0.f;
        g_tlabel[gtid] = 0;
        g_tvalid[gtid] = 0;
    }
    if (gtid == 0) g_ncand = 0;
    grid_bar();

    // ---------- phase 1: per-row max/argmax + histogram (2-row unroll) ----------
    for (int r = gw; r < M; r += 2 * NW) {
        float v1; int b1;
        score_row(cls + (long long)r * C, C, lane, v1, b1);
        int r2 = r + NW;
        float v2 = 0.f; int b2 = 0;
        if (r2 < M) score_row(cls + (long long)r2 * C, C, lane, v2, b2);
        if (lane == 0) {
            unsigned int o1 = f2ord(v1);
            g_ordered[r] = o1; g_label[r] = b1;
            atomicAdd(&g_hist[o1 >> ORD_SHIFT], 1u);
            if (r2 < M) {
                unsigned int o2 = f2ord(v2);
                g_ordered[r2] = o2; g_label[r2] = b2;
                atomicAdd(&g_hist[o2 >> ORD_SHIFT], 1u);
            }
        }
    }
    grid_bar();

    // ---------- phase 2: threshold bin (block 0) ----------
    if (bid == 0) {
        int* cs = (int*)s_u64;                  // 512 ints
        int s = 0;
        const uint4* h4 = (const uint4*)&g_hist[tid * 128];   // 128 bins/thread
        #pragma unroll
        for (int q = 0; q < 32; q++) {
            uint4 u = h4[q];
            s += (int)(u.x + u.y + u.z + u.w);
        }
        cs[tid] = s;
        __syncthreads();
        if (tid < 32) {
            int ws = 0;
            #pragma unroll
            for (int k = 0; k < 16; k++) ws += cs[tid * 16 + k];
            int suf = ws;
            #pragma unroll
            for (int off = 1; off < 32; off <<= 1) {
                int v = __shfl_down_sync(0xffffffffu, suf, off);
                if (tid + off < 32) suf += v;
            }
            int above = __shfl_down_sync(0xffffffffu, suf, 1);
            if (tid == 31) above = 0;
            if (tid == 0 && suf < TOPK) g_B = 0;
            if (suf >= TOPK && above < TOPK) {
                int acc = above;
                for (int ch = tid * 16 + 15; ch >= tid * 16; --ch) {
                    int c = cs[ch];
                    if (acc + c >= TOPK) {
                        int a2 = acc;
                        for (int b = ch * 128 + 127; b >= ch * 128; --b) {
                            a2 += (int)g_hist[b];
                            if (a2 >= TOPK) { g_B = b; break; }
                        }
                        break;
                    }
                    acc += c;
                }
            }
        }
    }
    grid_bar();

    // ---------- phase 3: compact (warp-aggregated) ----------
    {
        int B = g_B;
        int iters = (M + nthr - 1) / nthr;
        for (int it = 0; it < iters; it++) {
            int m = it * nthr + gtid;
            unsigned int o = (m < M) ? g_ordered[m] : 0u;
            bool pred = (m < M) && ((int)(o >> ORD_SHIFT) >= B);
            unsigned int bal = __ballot_sync(0xffffffffu, pred);
            if (bal) {
                int leader = __ffs(bal) - 1;
                int base = 0;
                if (lane == leader) base = atomicAdd(&g_ncand, __popc(bal));
                base = __shfl_sync(0xffffffffu, base, leader);
                if (pred) {
                    int p = base + __popc(bal & ((1u << lane) - 1u));
                    if (p < CAND_CAP)
                        g_cand[p] = ((unsigned long long)o << 20) |
                                    (unsigned long long)(0xFFFFFu - (unsigned)m);
                }
            }
        }
    }
    grid_bar();

    // ---------- phase 4: rank-select + decode (blocks 0..31) ----------
    if (bid < 32) {
        for (int v = tid; v < CAND_CAP; v += NTHR) s_u64[v] = g_cand[v];
        __syncthreads();
        int cand = bid * 64 + (tid >> 3);       // 64 candidates / block
        int part = tid & 7;                      // 8 threads / candidate
        unsigned long long my = s_u64[cand];
        int rank = 0;
        int jb = part * 256;
        #pragma unroll 8
        for (int j = 0; j < 256; j++) rank += (s_u64[jb + j] > my) ? 1 : 0;
        rank += __shfl_down_sync(0xffffffffu, rank, 4, 8);
        rank += __shfl_down_sync(0xffffffffu, rank, 2, 8);
        rank += __shfl_down_sync(0xffffffffu, rank, 1, 8);
        if (part == 0 && my != 0ULL && rank < TOPK) {
            int m = (int)(0xFFFFFu - (unsigned)(my & 0xFFFFFu));
            unsigned int o = (unsigned int)(my >> 20);
            float logit = ord2f(o);
            float score = 1.0f / (1.0f + expf(-logit));
            int label = g_label[m];
            const float4 r4 = ((const float4*)reg)[m];
            int a    = m % A;
            int cell = m / A;
            int w = pW ? *pW : w_fb;
            int x = cell % w, y = cell / w;
            float ax = ((float)x + 0.5f) * STRIDE_F;
            float ay = ((float)y + 0.5f) * STRIDE_F;
            float aw = anchor_size[a * 2 + 0];
            float ah = anchor_size[a * 2 + 1];
            float offx = fminf(fmaxf(r4.x * aw, -CTR_CLAMP_F), CTR_CLAMP_F);
            float offy = fminf(fmaxf(r4.y * ah, -CTR_CLAMP_F), CTR_CLAMP_F);
            float cx = ax + offx, cy = ay + offy;
            float bw = aw * expf(fminf(r4.z, SCALE_CLAMP_F));
            float bh = ah * expf(fminf(r4.w, SCALE_CLAMP_F));
            float4 box = make_float4(cx - 0.5f * bw, cy - 0.5f * bh,
                                     cx + 0.5f * bw, cy + 0.5f * bh);
            float offc = (float)label * 100000.0f;
            float4 ob = make_float4(box.x + offc, box.y + offc,
                                    box.z + offc, box.w + offc);
            g_tbox[rank]   = box;
            g_obox[rank]   = ob;
            g_area[rank]   = (ob.z - ob.x) * (ob.w - ob.y);
            g_tscore[rank] = score;
            g_tlabel[rank] = label;
            g_tvalid[rank] = (score >= CONF_T) ? 1 : 0;
        }
    }
    grid_bar();

    // ---------- phase 5: suppression mask (transposed) ----------
    for (int u = gtid; u < 16 * 1024; u += nthr) {
        int w = u >> 10;
        int i = u & 1023;
        if (i >= TOPK) continue;
        float4 bi4 = g_obox[i];
        float ai = g_area[i];
        unsigned long long bits = 0ULL;
        int jbase = w * 64;
        if (jbase + 63 > i) {
            #pragma unroll 4
            for (int b = 0; b < 64; b++) {
                int j = jbase + b;
                if (j > i && j < TOPK) {
                    float4 bj = g_obox[j];
                    float xx1 = fmaxf(bi4.x, bj.x);
                    float yy1 = fmaxf(bi4.y, bj.y);
                    float xx2 = fminf(bi4.z, bj.z);
                    float yy2 = fminf(bi4.w, bj.w);
                    float inter = fmaxf(1e-28f, xx2 - xx1) * fmaxf(1e-28f, yy2 - yy1);
                    float iou = inter / (ai + g_area[j] - inter + 1e-14f);
                    if (iou > NMS_T) bits |= (1ULL << b);
                }
            }
        }
        g_maskT[w * 1024 + i] = bits;
    }
    grid_bar();

    // ---------- phase 6: greedy NMS + outputs (block 0) ----------
    if (bid != 0) return;

    unsigned long long* diag_s = s_u64;     // 1024 u64
    for (int i = tid; i < TOPK; i += NTHR)
        diag_s[i] = g_maskT[(i >> 6) * 1024 + i];
    if (tid < 16) {
        unsigned long long vw = 0ULL;
        #pragma unroll 4
        for (int k = 0; k < 64; k++) {
            int i = tid * 64 + k;
            if (i < TOPK && g_tvalid[i]) vw |= (1ULL << k);
        }
        s_validw[tid] = vw;
        s_rem[tid] = 0ULL;
        s_keep[tid] = 0ULL;
    }
    __syncthreads();

    for (int c = 0; c < 16; c++) {
        unsigned long long m0 = 0ULL, m1 = 0ULL;
        bool owner = (wid >= 1) && (wid < 16) && (wid > c);
        if (owner) {
            int r0 = c * 64 + 2 * lane;
            m0 = g_maskT[wid * 1024 + r0];
            m1 = g_maskT[wid * 1024 + r0 + 1];
        }
        if (tid == 0) {
            unsigned long long alive = s_validw[c] & ~s_rem[c];
            unsigned long long keepw = 0ULL;
            while (alive) {
                int b = __ffsll((long long)alive) - 1;
                keepw |= (1ULL << b);
                unsigned long long d = diag_s[c * 64 + b];
                alive &= ~(d | (1ULL << b));
            }
            s_keep[c] = keepw;
        }
        __syncthreads();
        if (owner) {
            unsigned long long kw = s_keep[c];
            unsigned long long acc =
                (((kw >> (2 * lane)) & 1ULL) ? m0 : 0ULL) |
                (((kw >> (2 * lane + 1)) & 1ULL) ? m1 : 0ULL);
            #pragma unroll
            for (int off = 16; off > 0; off >>= 1)
                acc |= __shfl_down_sync(0xffffffffu, acc, off);
            if (lane == 0) s_rem[wid] |= acc;
        }
        __syncthreads();
    }

    int W = pW ? *pW : w_fb;
    int H = pH ? *pH : h_fb;
    float img_w = (float)W * STRIDE_F;
    float img_h = (float)H * STRIDE_F;
    for (int i = tid; i < TOPK; i += NTHR) {
        bool keep = (s_keep[i >> 6] >> (i & 63)) & 1ULL;
        float kf = keep ? 1.0f : 0.0f;
        float4 b = g_tbox[i];
        out[i * 4 + 0] = fminf(fmaxf(b.x / img_w, 0.f), 1.f) * kf;
        out[i * 4 + 1] = fminf(fmaxf(b.y / img_h, 0.f), 1.f) * kf;
        out[i * 4 + 2] = fminf(fmaxf(b.z / img_w, 0.f), 1.f) * kf;
        out[i * 4 + 3] = fminf(fmaxf(b.w / img_h, 0.f), 1.f) * kf;
        out[4 * TOPK + i] = g_tscore[i] * kf;
        out[5 * TOPK + i] = keep ? (float)g_tlabel[i] : -1.0f;
        out[6 * TOPK + i] = kf;
    }
}

// ---------------- launch ----------------
extern "C" void kernel_launch(void* const* d_in, const int* in_sizes, int n_in,
                              void* d_out, int out_size) {
    const float* cls  = (const float*)d_in[0];
    const float* reg  = (const float*)d_in[1];
    const float* anch = (const float*)d_in[2];
    const int* pH = (n_in > 3) ? (const int*)d_in[3] : nullptr;
    const int* pW = (n_in > 4) ? (const int*)d_in[4] : nullptr;

    int M = in_sizes[1] / 4;
    int C = in_sizes[0] / M;
    int A = in_sizes[2] / 2;

    int cells = M / A;
    int w_guess = 1;
    while ((w_guess + 1) * (w_guess + 1) <= cells) w_guess++;
    int h_guess = cells / w_guess;

    fused_yolof<<<NBLK, NTHR>>>(cls, reg, anch, pH, pW,
                                h_guess, w_guess, A, M, C, (float*)d_out);
}

// round 5
// speedup vs baseline: 1.0260x; 1.0260x over previous
#include <cuda_runtime.h>
#include <cuda_bf16.h>
#include <math.h>

// ---------------- constants ----------------
#define TOPK        1000
#define CAND_CAP    2048
#define HB          65536
#define ORD_SHIFT   16
#define MCAP        (1 << 17)
#define NMS_T       0.6f
#define CONF_T      0.05f
#define CTR_CLAMP_F 32.0f
#define STRIDE_F    32.0f
#define SCALE_CLAMP_F 4.1351666f   // log(1000/16) fp32

#define NBLK  132
#define NTHR  512

// ---------------- device scratch ----------------
__device__ unsigned int       g_ordered[MCAP];
__device__ int                g_label[MCAP];
__device__ unsigned int       g_hist[HB];
__device__ unsigned long long g_cand[CAND_CAP];
__device__ int                g_ncand;
__device__ int                g_B;
__device__ float4             g_tbox[1024];
__device__ float4             g_obox[1024];
__device__ float              g_area[1024];
__device__ float              g_tscore[1024];
__device__ int                g_tlabel[1024];
__device__ unsigned char      g_tvalid[1024];
__device__ unsigned long long g_maskT[16 * 1024];   // maskT[w*1024 + i]

// grid barrier state
__device__ unsigned int g_bar_count = 0;
__device__ unsigned int g_bar_gen   = 0;

__device__ __forceinline__ void grid_bar() {
    __syncthreads();
    if (threadIdx.x == 0) {
        __threadfence();
        volatile unsigned int* vgen = &g_bar_gen;
        unsigned int gen = *vgen;
        unsigned int t = atomicAdd(&g_bar_count, 1u);
        if (t == (unsigned)(gridDim.x - 1)) {
            g_bar_count = 0;
            __threadfence();
            *vgen = gen + 1u;
        } else {
            while (*vgen == gen) __nanosleep(32);
        }
        __threadfence();
    }
    __syncthreads();
}

__device__ __forceinline__ unsigned int f2ord(float f) {
    unsigned int u = __float_as_uint(f);
    return (u & 0x80000000u) ? ~u : (u | 0x80000000u);
}
__device__ __forceinline__ float ord2f(unsigned int o) {
    unsigned int u = (o & 0x80000000u) ? (o & 0x7FFFFFFFu) : ~o;
    return __uint_as_float(u);
}

// generic-C fallback (rolled loop)
__device__ __forceinline__ void score_row_gen(const float* __restrict__ row, int C, int lane,
                                              float& v, int& bi) {
    v = -INFINITY; bi = 0;
    for (int c = lane; c < C; c += 32) {
        float x = row[c];
        if (x > v) { v = x; bi = c; }
    }
    #pragma unroll
    for (int off = 16; off > 0; off >>= 1) {
        float ov = __shfl_down_sync(0xffffffffu, v, off);
        int   ob = __shfl_down_sync(0xffffffffu, bi, off);
        if (ov > v || (ov == v && ob < bi)) { v = ov; bi = ob; }
    }
}

// =====================================================================
__global__ __launch_bounds__(NTHR, 1) void fused_yolof(
    const float* __restrict__ cls, const float* __restrict__ reg,
    const float* __restrict__ anchor_size,
    const int* __restrict__ pH, const int* __restrict__ pW,
    int h_fb, int w_fb, int A, int M, int C,
    float* __restrict__ out)
{
    __shared__ unsigned long long s_u64[CAND_CAP];          // 16KB, phase-aliased
    __shared__ unsigned long long s_validw[16], s_rem[16], s_keep[16];

    const int bid  = blockIdx.x;
    const int tid  = threadIdx.x;
    const int gtid = bid * NTHR + tid;
    const int nthr = NBLK * NTHR;
    const int lane = tid & 31;
    const int wid  = tid >> 5;
    const int gw   = gtid >> 5;
    const int NW   = nthr >> 5;

    // ---------- phase 0: zero ----------
    for (int i = gtid; i < HB; i += nthr) g_hist[i] = 0;
    for (int i = gtid; i < CAND_CAP; i += nthr) g_cand[i] = 0ULL;
    if (gtid < 1024) {
        g_tbox[gtid]   = make_float4(0.f, 0.f, 0.f, 0.f);
        g_obox[gtid]   = make_float4(0.f, 0.f, 0.f, 0.f);
        g_area[gtid]   = 0.f;
        g_tscore[gtid] = 0.f;
        g_tlabel[gtid] = 0;
        g_tvalid[gtid] = 0;
    }
    if (gtid == 0) g_ncand = 0;
    grid_bar();

    // ---------- phase 1: per-row max/argmax + histogram ----------
    if (C == 80) {
        // 4 consecutive rows per warp, 12 LDGs in flight, REDUX reductions
        for (int r0 = gw * 4; r0 < M; r0 += NW * 4) {
            const float* p0 = cls + (size_t)r0 * 80;
            bool third = (lane < 16);
            // issue all loads up front (fully unrolled, independent)
            float f0[4], f1[4], f2[4];
            #pragma unroll
            for (int k = 0; k < 4; k++) {
                bool ok = (r0 + k) < M;
                const float* row = p0 + k * 80;
                f0[k] = ok ? row[lane]      : -INFINITY;
                f1[k] = ok ? row[lane + 32] : -INFINITY;
                f2[k] = (ok && third) ? row[lane + 64] : -INFINITY;
            }
            unsigned int my_o = 0; int my_b = 0;
            #pragma unroll
            for (int k = 0; k < 4; k++) {
                float v = f0[k]; int bi = lane;
                if (f1[k] > v) { v = f1[k]; bi = lane + 32; }
                if (f2[k] > v) { v = f2[k]; bi = lane + 64; }
                unsigned int o  = f2ord(v);
                unsigned int om = __reduce_max_sync(0xffffffffu, o);
                int cand = (o == om) ? bi : 0x7fffffff;
                int argm = __reduce_min_sync(0xffffffffu, cand);
                if (lane == k) { my_o = om; my_b = argm; }
            }
            int r = r0 + lane;
            if (lane < 4 && r < M) {
                g_ordered[r] = my_o;
                g_label[r]   = my_b;
                atomicAdd(&g_hist[my_o >> ORD_SHIFT], 1u);
            }
        }
    } else {
        for (int r = gw; r < M; r += NW) {
            float v; int bi;
            score_row_gen(cls + (size_t)r * C, C, lane, v, bi);
            if (lane == 0) {
                unsigned int o = f2ord(v);
                g_ordered[r] = o; g_label[r] = bi;
                atomicAdd(&g_hist[o >> ORD_SHIFT], 1u);
            }
        }
    }
    grid_bar();

    // ---------- phase 2: threshold bin (block 0) ----------
    if (bid == 0) {
        int* cs = (int*)s_u64;                  // 512 ints
        int s = 0;
        const uint4* h4 = (const uint4*)&g_hist[tid * 128];   // 128 bins/thread
        #pragma unroll
        for (int q = 0; q < 32; q++) {
            uint4 u = h4[q];
            s += (int)(u.x + u.y + u.z + u.w);
        }
        cs[tid] = s;
        __syncthreads();
        if (tid < 32) {
            int ws = 0;
            #pragma unroll
            for (int k = 0; k < 16; k++) ws += cs[tid * 16 + k];
            int suf = ws;
            #pragma unroll
            for (int off = 1; off < 32; off <<= 1) {
                int v = __shfl_down_sync(0xffffffffu, suf, off);
                if (tid + off < 32) suf += v;
            }
            int above = __shfl_down_sync(0xffffffffu, suf, 1);
            if (tid == 31) above = 0;
            if (tid == 0 && suf < TOPK) g_B = 0;
            if (suf >= TOPK && above < TOPK) {
                int acc = above;
                for (int ch = tid * 16 + 15; ch >= tid * 16; --ch) {
                    int c = cs[ch];
                    if (acc + c >= TOPK) {
                        int a2 = acc;
                        for (int b = ch * 128 + 127; b >= ch * 128; --b) {
                            a2 += (int)g_hist[b];
                            if (a2 >= TOPK) { g_B = b; break; }
                        }
                        break;
                    }
                    acc += c;
                }
            }
        }
    }
    grid_bar();

    // ---------- phase 3: compact (warp-aggregated) ----------
    {
        int B = g_B;
        int iters = (M + nthr - 1) / nthr;
        for (int it = 0; it < iters; it++) {
            int m = it * nthr + gtid;
            unsigned int o = (m < M) ? g_ordered[m] : 0u;
            bool pred = (m < M) && ((int)(o >> ORD_SHIFT) >= B);
            unsigned int bal = __ballot_sync(0xffffffffu, pred);
            if (bal) {
                int leader = __ffs(bal) - 1;
                int base = 0;
                if (lane == leader) base = atomicAdd(&g_ncand, __popc(bal));
                base = __shfl_sync(0xffffffffu, base, leader);
                if (pred) {
                    int p = base + __popc(bal & ((1u << lane) - 1u));
                    if (p < CAND_CAP)
                        g_cand[p] = ((unsigned long long)o << 20) |
                                    (unsigned long long)(0xFFFFFu - (unsigned)m);
                }
            }
        }
    }
    grid_bar();

    // ---------- phase 4: rank-select + decode (blocks 0..31) ----------
    if (bid < 32) {
        for (int v = tid; v < CAND_CAP; v += NTHR) s_u64[v] = g_cand[v];
        __syncthreads();
        int cand = bid * 64 + (tid >> 3);       // 64 candidates / block
        int part = tid & 7;                      // 8 threads / candidate
        unsigned long long my = s_u64[cand];
        int rank = 0;
        int jb = part * 256;
        #pragma unroll 8
        for (int j = 0; j < 256; j++) rank += (s_u64[jb + j] > my) ? 1 : 0;
        rank += __shfl_down_sync(0xffffffffu, rank, 4, 8);
        rank += __shfl_down_sync(0xffffffffu, rank, 2, 8);
        rank += __shfl_down_sync(0xffffffffu, rank, 1, 8);
        if (part == 0 && my != 0ULL && rank < TOPK) {
            int m = (int)(0xFFFFFu - (unsigned)(my & 0xFFFFFu));
            unsigned int o = (unsigned int)(my >> 20);
            float logit = ord2f(o);
            float score = 1.0f / (1.0f + expf(-logit));
            int label = g_label[m];
            const float4 r4 = ((const float4*)reg)[m];
            int a    = m % A;
            int cell = m / A;
            int w = pW ? *pW : w_fb;
            int x = cell % w, y = cell / w;
            float ax = ((float)x + 0.5f) * STRIDE_F;
            float ay = ((float)y + 0.5f) * STRIDE_F;
            float aw = anchor_size[a * 2 + 0];
            float ah = anchor_size[a * 2 + 1];
            float offx = fminf(fmaxf(r4.x * aw, -CTR_CLAMP_F), CTR_CLAMP_F);
            float offy = fminf(fmaxf(r4.y * ah, -CTR_CLAMP_F), CTR_CLAMP_F);
            float cx = ax + offx, cy = ay + offy;
            float bw = aw * expf(fminf(r4.z, SCALE_CLAMP_F));
            float bh = ah * expf(fminf(r4.w, SCALE_CLAMP_F));
            float4 box = make_float4(cx - 0.5f * bw, cy - 0.5f * bh,
                                     cx + 0.5f * bw, cy + 0.5f * bh);
            float offc = (float)label * 100000.0f;
            float4 ob = make_float4(box.x + offc, box.y + offc,
                                    box.z + offc, box.w + offc);
            g_tbox[rank]   = box;
            g_obox[rank]   = ob;
            g_area[rank]   = (ob.z - ob.x) * (ob.w - ob.y);
            g_tscore[rank] = score;
            g_tlabel[rank] = label;
            g_tvalid[rank] = (score >= CONF_T) ? 1 : 0;
        }
    }
    grid_bar();

    // ---------- phase 5: suppression mask (transposed) ----------
    for (int u = gtid; u < 16 * 1024; u += nthr) {
        int w = u >> 10;
        int i = u & 1023;
        if (i >= TOPK) continue;
        float4 bi4 = g_obox[i];
        float ai = g_area[i];
        unsigned long long bits = 0ULL;
        int jbase = w * 64;
        if (jbase + 63 > i) {
            #pragma unroll 4
            for (int b = 0; b < 64; b++) {
                int j = jbase + b;
                if (j > i && j < TOPK) {
                    float4 bj = g_obox[j];
                    float xx1 = fmaxf(bi4.x, bj.x);
                    float yy1 = fmaxf(bi4.y, bj.y);
                    float xx2 = fminf(bi4.z, bj.z);
                    float yy2 = fminf(bi4.w, bj.w);
                    float inter = fmaxf(1e-28f, xx2 - xx1) * fmaxf(1e-28f, yy2 - yy1);
                    float iou = inter / (ai + g_area[j] - inter + 1e-14f);
                    if (iou > NMS_T) bits |= (1ULL << b);
                }
            }
        }
        g_maskT[w * 1024 + i] = bits;
    }
    grid_bar();

    // ---------- phase 6: greedy NMS + outputs (block 0) ----------
    if (bid != 0) return;

    unsigned long long* diag_s = s_u64;     // 1024 u64
    for (int i = tid; i < TOPK; i += NTHR)
        diag_s[i] = g_maskT[(i >> 6) * 1024 + i];
    if (tid < 16) {
        unsigned long long vw = 0ULL;
        #pragma unroll 4
        for (int k = 0; k < 64; k++) {
            int i = tid * 64 + k;
            if (i < TOPK && g_tvalid[i]) vw |= (1ULL << k);
        }
        s_validw[tid] = vw;
        s_rem[tid] = 0ULL;
        s_keep[tid] = 0ULL;
    }
    __syncthreads();

    for (int c = 0; c < 16; c++) {
        unsigned long long m0 = 0ULL, m1 = 0ULL;
        bool owner = (wid >= 1) && (wid < 16) && (wid > c);
        if (owner) {
            int r0 = c * 64 + 2 * lane;
            m0 = g_maskT[wid * 1024 + r0];
            m1 = g_maskT[wid * 1024 + r0 + 1];
        }
        if (tid == 0) {
            unsigned long long alive = s_validw[c] & ~s_rem[c];
            unsigned long long keepw = 0ULL;
            while (alive) {
                int b = __ffsll((long long)alive) - 1;
                keepw |= (1ULL << b);
                unsigned long long d = diag_s[c * 64 + b];
                alive &= ~(d | (1ULL << b));
            }
            s_keep[c] = keepw;
        }
        __syncthreads();
        if (owner) {
            unsigned long long kw = s_keep[c];
            unsigned long long acc =
                (((kw >> (2 * lane)) & 1ULL) ? m0 : 0ULL) |
                (((kw >> (2 * lane + 1)) & 1ULL) ? m1 : 0ULL);
            #pragma unroll
            for (int off = 16; off > 0; off >>= 1)
                acc |= __shfl_down_sync(0xffffffffu, acc, off);
            if (lane == 0) s_rem[wid] |= acc;
        }
        __syncthreads();
    }

    int W = pW ? *pW : w_fb;
    int H = pH ? *pH : h_fb;
    float img_w = (float)W * STRIDE_F;
    float img_h = (float)H * STRIDE_F;
    for (int i = tid; i < TOPK; i += NTHR) {
        bool keep = (s_keep[i >> 6] >> (i & 63)) & 1ULL;
        float kf = keep ? 1.0f : 0.0f;
        float4 b = g_tbox[i];
        out[i * 4 + 0] = fminf(fmaxf(b.x / img_w, 0.f), 1.f) * kf;
        out[i * 4 + 1] = fminf(fmaxf(b.y / img_h, 0.f), 1.f) * kf;
        out[i * 4 + 2] = fminf(fmaxf(b.z / img_w, 0.f), 1.f) * kf;
        out[i * 4 + 3] = fminf(fmaxf(b.w / img_h, 0.f), 1.f) * kf;
        out[4 * TOPK + i] = g_tscore[i] * kf;
        out[5 * TOPK + i] = keep ? (float)g_tlabel[i] : -1.0f;
        out[6 * TOPK + i] = kf;
    }
}

// ---------------- launch ----------------
extern "C" void kernel_launch(void* const* d_in, const int* in_sizes, int n_in,
                              void* d_out, int out_size) {
    const float* cls  = (const float*)d_in[0];
    const float* reg  = (const float*)d_in[1];
    const float* anch = (const float*)d_in[2];
    const int* pH = (n_in > 3) ? (const int*)d_in[3] : nullptr;
    const int* pW = (n_in > 4) ? (const int*)d_in[4] : nullptr;

    int M = in_sizes[1] / 4;
    int C = in_sizes[0] / M;
    int A = in_sizes[2] / 2;

    int cells = M / A;
    int w_guess = 1;
    while ((w_guess + 1) * (w_guess + 1) <= cells) w_guess++;
    int h_guess = cells / w_guess;

    fused_yolof<<<NBLK, NTHR>>>(cls, reg, anch, pH, pW,
                                h_guess, w_guess, A, M, C, (float*)d_out);
}

// round 6
// speedup vs baseline: 1.1594x; 1.1300x over previous
#include <cuda_runtime.h>
#include <cuda_bf16.h>
#include <math.h>

// ---------------- constants ----------------
#define TOPK        1000
#define CAND_CAP    2048
#define HB          65536
#define ORD_SHIFT   16
#define MCAP        (1 << 17)
#define NMS_T       0.6f
#define CONF_T      0.05f
#define CTR_CLAMP_F 32.0f
#define STRIDE_F    32.0f
#define SCALE_CLAMP_F 4.1351666f   // log(1000/16) fp32

#define ROWS_PER_BLK 64

// ---------------- device scratch ----------------
__device__ unsigned int       g_ordered[MCAP];
__device__ int                g_label[MCAP];
__device__ unsigned int       g_hist[HB];
__device__ unsigned long long g_cand[CAND_CAP];
__device__ int                g_ncand;
__device__ int                g_B;
__device__ float4             g_tbox[1024];
__device__ float4             g_obox[1024];
__device__ float              g_area[1024];
__device__ float              g_tscore[1024];
__device__ int                g_tlabel[1024];
__device__ unsigned char      g_tvalid[1024];
__device__ unsigned long long g_maskT[16 * 1024];   // maskT[w*1024 + i]

__device__ __forceinline__ unsigned int f2ord(float f) {
    unsigned int u = __float_as_uint(f);
    return (u & 0x80000000u) ? ~u : (u | 0x80000000u);
}
__device__ __forceinline__ float ord2f(unsigned int o) {
    unsigned int u = (o & 0x80000000u) ? (o & 0x7FFFFFFFu) : ~o;
    return __uint_as_float(u);
}

// ---------------- K0: zero scratch ----------------
__global__ void k0_zero() {
    int tid = blockIdx.x * blockDim.x + threadIdx.x;
    int n = gridDim.x * blockDim.x;
    for (int i = tid; i < HB; i += n) g_hist[i] = 0;
    for (int i = tid; i < CAND_CAP; i += n) g_cand[i] = 0ULL;
    if (tid < 1024) {
        g_tbox[tid]   = make_float4(0.f, 0.f, 0.f, 0.f);
        g_obox[tid]   = make_float4(0.f, 0.f, 0.f, 0.f);
        g_area[tid]   = 0.f;
        g_tscore[tid] = 0.f;
        g_tlabel[tid] = 0;
        g_tvalid[tid] = 0;
    }
    if (tid == 0) g_ncand = 0;
}

// ---------------- K1 (C==80): staged deep-MLP streamer ----------------
// Block: 256 threads, 64 contiguous rows (20KB). 5 independent coalesced
// float4 LDGs per thread -> smem (stride 84 floats, conflict-free), then
// 8 warps reduce 8 rows each via REDUX max + first-index tie-break.
__global__ __launch_bounds__(256) void k1_scores80(const float* __restrict__ cls, int M) {
    __shared__ float s[ROWS_PER_BLK * 84];
    int base_row = blockIdx.x * ROWS_PER_BLK;
    int nrows = M - base_row;
    if (nrows > ROWS_PER_BLK) nrows = ROWS_PER_BLK;
    int tid = threadIdx.x;

    const float4* src = (const float4*)(cls + (size_t)base_row * 80);
    int nf4 = nrows * 20;
    #pragma unroll
    for (int q = 0; q < 5; q++) {
        int i = tid + q * 256;
        if (i < nf4) {
            float4 v = src[i];                 // coalesced, independent
            int g = i * 4;
            int r = g / 80;
            int c = g - r * 80;                // multiple of 4; never spans rows
            *(float4*)&s[r * 84 + c] = v;
        }
    }
    __syncthreads();

    int wid = tid >> 5, lane = tid & 31;
    #pragma unroll
    for (int rr = 0; rr < 8; rr++) {
        int r = wid * 8 + rr;                  // warp-uniform
        if (r >= nrows) break;
        float v0 = s[r * 84 + lane];
        float v1 = s[r * 84 + lane + 32];
        float v2 = (lane < 16) ? s[r * 84 + lane + 64] : -INFINITY;
        float v = v0; int bi = lane;
        if (v1 > v) { v = v1; bi = lane + 32; }
        if (v2 > v) { v = v2; bi = lane + 64; }
        unsigned int o  = f2ord(v);
        unsigned int om = __reduce_max_sync(0xffffffffu, o);
        int cand = (o == om) ? bi : 0x7fffffff;
        int argm = __reduce_min_sync(0xffffffffu, cand);
        if (lane == 0) {
            int row = base_row + r;
            g_ordered[row] = om;
            g_label[row]   = argm;
            atomicAdd(&g_hist[om >> ORD_SHIFT], 1u);
        }
    }
}

// generic-C fallback
__global__ __launch_bounds__(256) void k1_scores_gen(const float* __restrict__ cls, int M, int C) {
    int warp = blockIdx.x * (blockDim.x >> 5) + (threadIdx.x >> 5);
    int lane = threadIdx.x & 31;
    if (warp >= M) return;
    const float* row = cls + (long long)warp * C;
    float v = -INFINITY; int bi = 0;
    for (int c = lane; c < C; c += 32) {
        float x = row[c];
        if (x > v) { v = x; bi = c; }
    }
    #pragma unroll
    for (int off = 16; off > 0; off >>= 1) {
        float ov = __shfl_down_sync(0xffffffffu, v, off);
        int   ob = __shfl_down_sync(0xffffffffu, bi, off);
        if (ov > v || (ov == v && ob < bi)) { v = ov; bi = ob; }
    }
    if (lane == 0) {
        unsigned int o = f2ord(v);
        g_ordered[warp] = o;
        g_label[warp] = bi;
        atomicAdd(&g_hist[o >> ORD_SHIFT], 1u);
    }
}

// ---------------- K2: find threshold bin B ----------------
__global__ __launch_bounds__(1024) void k2_scan() {
    __shared__ int cs[1024];
    int t = threadIdx.x;
    int s = 0;
    const uint4* h4 = (const uint4*)&g_hist[t * 64];
    #pragma unroll
    for (int q = 0; q < 16; q++) {
        uint4 u = h4[q];
        s += (int)(u.x + u.y + u.z + u.w);
    }
    cs[t] = s;
    __syncthreads();
    if (t < 32) {
        int ws = 0;
        #pragma unroll
        for (int k = 0; k < 32; k++) ws += cs[t * 32 + k];
        int suf = ws;
        #pragma unroll
        for (int off = 1; off < 32; off <<= 1) {
            int v = __shfl_down_sync(0xffffffffu, suf, off);
            if (t + off < 32) suf += v;
        }
        int above = __shfl_down_sync(0xffffffffu, suf, 1);
        if (t == 31) above = 0;
        if (t == 0 && suf < TOPK) g_B = 0;
        if (suf >= TOPK && above < TOPK) {
            int acc = above;
            for (int ch = t * 32 + 31; ch >= t * 32; --ch) {
                int c = cs[ch];
                if (acc + c >= TOPK) {
                    int a2 = acc;
                    for (int b = ch * 64 + 63; b >= ch * 64; --b) {
                        a2 += (int)g_hist[b];
                        if (a2 >= TOPK) { g_B = b; break; }
                    }
                    break;
                }
                acc += c;
            }
        }
    }
}

// ---------------- K3: compact (warp-aggregated atomics) ----------------
__global__ __launch_bounds__(256) void k3_compact(int M) {
    int m = blockIdx.x * blockDim.x + threadIdx.x;
    int lane = threadIdx.x & 31;
    unsigned int o = (m < M) ? g_ordered[m] : 0u;
    bool pred = (m < M) && ((int)(o >> ORD_SHIFT) >= g_B);
    unsigned int bal = __ballot_sync(0xffffffffu, pred);
    if (!bal) return;
    int leader = __ffs(bal) - 1;
    int base = 0;
    if (lane == leader) base = atomicAdd(&g_ncand, __popc(bal));
    base = __shfl_sync(0xffffffffu, base, leader);
    if (pred) {
        int off = __popc(bal & ((1u << lane) - 1u));
        int p = base + off;
        if (p < CAND_CAP) {
            g_cand[p] = ((unsigned long long)o << 20) |
                        (unsigned long long)(0xFFFFFu - (unsigned)m);
        }
    }
}

// ---------------- K4: rank-select + decode (fused) ----------------
__global__ __launch_bounds__(256) void k4_rank_decode(
    const float* __restrict__ reg, const float* __restrict__ anchor_size,
    const int* __restrict__ pW, int w_fallback, int A, int M)
{
    __shared__ unsigned long long sk[CAND_CAP];
    int tid = threadIdx.x;
    for (int v = tid; v < CAND_CAP; v += 256) sk[v] = g_cand[v];
    __syncthreads();

    int cand = blockIdx.x * 64 + (tid >> 2);
    int part = tid & 3;
    unsigned long long my = sk[cand];
    int rank = 0;
    int jb = part * 512;
    #pragma unroll 8
    for (int j = 0; j < 512; j++) rank += (sk[jb + j] > my) ? 1 : 0;
    rank += __shfl_down_sync(0xffffffffu, rank, 2, 4);
    rank += __shfl_down_sync(0xffffffffu, rank, 1, 4);

    if (part == 0 && my != 0ULL && rank < TOPK) {
        int m = (int)(0xFFFFFu - (unsigned)(my & 0xFFFFFu));
        unsigned int o = (unsigned int)(my >> 20);
        float logit = ord2f(o);
        float score = 1.0f / (1.0f + expf(-logit));
        int label = g_label[m];
        const float4 r4 = ((const float4*)reg)[m];
        int a    = m % A;
        int cell = m / A;
        int w = pW ? *pW : w_fallback;
        int x = cell % w, y = cell / w;
        float ax = ((float)x + 0.5f) * STRIDE_F;
        float ay = ((float)y + 0.5f) * STRIDE_F;
        float aw = anchor_size[a * 2 + 0];
        float ah = anchor_size[a * 2 + 1];
        float offx = fminf(fmaxf(r4.x * aw, -CTR_CLAMP_F), CTR_CLAMP_F);
        float offy = fminf(fmaxf(r4.y * ah, -CTR_CLAMP_F), CTR_CLAMP_F);
        float cx = ax + offx, cy = ay + offy;
        float bw = aw * expf(fminf(r4.z, SCALE_CLAMP_F));
        float bh = ah * expf(fminf(r4.w, SCALE_CLAMP_F));
        float4 box = make_float4(cx - 0.5f * bw, cy - 0.5f * bh,
                                 cx + 0.5f * bw, cy + 0.5f * bh);
        float offc = (float)label * 100000.0f;
        float4 ob = make_float4(box.x + offc, box.y + offc, box.z + offc, box.w + offc);
        g_tbox[rank]   = box;
        g_obox[rank]   = ob;
        g_area[rank]   = (ob.z - ob.x) * (ob.w - ob.y);
        g_tscore[rank] = score;
        g_tlabel[rank] = label;
        g_tvalid[rank] = (score >= CONF_T) ? 1 : 0;
    }
}

// ---------------- K5: suppression bitmask (transposed) ----------------
__global__ __launch_bounds__(256) void k5_mask() {
    int u = blockIdx.x * blockDim.x + threadIdx.x;
    int w = u >> 10;
    int i = u & 1023;
    if (i >= TOPK) return;
    float4 bi = g_obox[i];
    float ai = g_area[i];
    unsigned long long bits = 0ULL;
    int jbase = w * 64;
    if (jbase + 63 > i) {
        #pragma unroll 4
        for (int b = 0; b < 64; b++) {
            int j = jbase + b;
            if (j > i && j < TOPK) {
                float4 bj = g_obox[j];
                float xx1 = fmaxf(bi.x, bj.x);
                float yy1 = fmaxf(bi.y, bj.y);
                float xx2 = fminf(bi.z, bj.z);
                float yy2 = fminf(bi.w, bj.w);
                float inter = fmaxf(1e-28f, xx2 - xx1) * fmaxf(1e-28f, yy2 - yy1);
                float iou = inter / (ai + g_area[j] - inter + 1e-14f);
                if (iou > NMS_T) bits |= (1ULL << b);
            }
        }
    }
    g_maskT[w * 1024 + i] = bits;
}

// ---------------- K6: chunked ffs greedy NMS + outputs ----------------
__global__ __launch_bounds__(1024) void k6_nms_out(
    float* __restrict__ out,
    const int* __restrict__ pH, const int* __restrict__ pW,
    int h_fallback, int w_fallback)
{
    __shared__ unsigned long long diag_s[1024];
    __shared__ unsigned long long validw_s[16];
    __shared__ unsigned long long rem_s[16];
    __shared__ unsigned long long keep_s[16];
    int tid  = threadIdx.x;
    int wid  = tid >> 5;
    int lane = tid & 31;

    if (tid < TOPK) diag_s[tid] = g_maskT[(tid >> 6) * 1024 + tid];
    if (tid < 16) {
        unsigned long long vw = 0ULL;
        #pragma unroll 4
        for (int k = 0; k < 64; k++) {
            int i = tid * 64 + k;
            if (i < TOPK && g_tvalid[i]) vw |= (1ULL << k);
        }
        validw_s[tid] = vw;
        rem_s[tid] = 0ULL;
        keep_s[tid] = 0ULL;
    }
    __syncthreads();

    for (int c = 0; c < 16; c++) {
        unsigned long long m0 = 0ULL, m1 = 0ULL;
        bool owner = (wid >= 1) && (wid < 16) && (wid > c);
        if (owner) {
            int r0 = c * 64 + 2 * lane;
            m0 = g_maskT[wid * 1024 + r0];
            m1 = g_maskT[wid * 1024 + r0 + 1];
        }
        if (tid == 0) {
            unsigned long long alive = validw_s[c] & ~rem_s[c];
            unsigned long long keepw = 0ULL;
            while (alive) {
                int b = __ffsll((long long)alive) - 1;
                keepw |= (1ULL << b);
                unsigned long long d = diag_s[c * 64 + b];
                alive &= ~(d | (1ULL << b));
            }
            keep_s[c] = keepw;
        }
        __syncthreads();
        if (owner) {
            unsigned long long kw = keep_s[c];
            unsigned long long acc =
                (((kw >> (2 * lane)) & 1ULL) ? m0 : 0ULL) |
                (((kw >> (2 * lane + 1)) & 1ULL) ? m1 : 0ULL);
            #pragma unroll
            for (int off = 16; off > 0; off >>= 1)
                acc |= __shfl_down_sync(0xffffffffu, acc, off);
            if (lane == 0) rem_s[wid] |= acc;
        }
        __syncthreads();
    }

    if (tid < TOPK) {
        bool keep = (keep_s[tid >> 6] >> (tid & 63)) & 1ULL;
        float kf = keep ? 1.0f : 0.0f;
        int W = pW ? *pW : w_fallback;
        int H = pH ? *pH : h_fallback;
        float img_w = (float)W * STRIDE_F;
        float img_h = (float)H * STRIDE_F;
        float4 b = g_tbox[tid];
        out[tid * 4 + 0] = fminf(fmaxf(b.x / img_w, 0.f), 1.f) * kf;
        out[tid * 4 + 1] = fminf(fmaxf(b.y / img_h, 0.f), 1.f) * kf;
        out[tid * 4 + 2] = fminf(fmaxf(b.z / img_w, 0.f), 1.f) * kf;
        out[tid * 4 + 3] = fminf(fmaxf(b.w / img_h, 0.f), 1.f) * kf;
        out[4 * TOPK + tid] = g_tscore[tid] * kf;
        out[5 * TOPK + tid] = keep ? (float)g_tlabel[tid] : -1.0f;
        out[6 * TOPK + tid] = kf;
    }
}

// ---------------- launch ----------------
extern "C" void kernel_launch(void* const* d_in, const int* in_sizes, int n_in,
                              void* d_out, int out_size) {
    const float* cls  = (const float*)d_in[0];
    const float* reg  = (const float*)d_in[1];
    const float* anch = (const float*)d_in[2];
    const int* pH = (n_in > 3) ? (const int*)d_in[3] : nullptr;
    const int* pW = (n_in > 4) ? (const int*)d_in[4] : nullptr;

    int M = in_sizes[1] / 4;
    int C = in_sizes[0] / M;
    int A = in_sizes[2] / 2;

    int cells = M / A;
    int w_guess = 1;
    while ((w_guess + 1) * (w_guess + 1) <= cells) w_guess++;
    int h_guess = cells / w_guess;

    k0_zero<<<128, 256>>>();
    if (C == 80) {
        k1_scores80<<<(M + ROWS_PER_BLK - 1) / ROWS_PER_BLK, 256>>>(cls, M);
    } else {
        k1_scores_gen<<<(M + 7) / 8, 256>>>(cls, M, C);
    }
    k2_scan<<<1, 1024>>>();
    k3_compact<<<(M + 255) / 256, 256>>>(M);
    k4_rank_decode<<<32, 256>>>(reg, anch, pW, w_guess, A, M);
    k5_mask<<<64, 256>>>();
    k6_nms_out<<<1, 1024>>>((float*)d_out, pH, pW, h_guess, w_guess);
}